// round 13
// baseline (speedup 1.0000x reference)
#include <cuda_runtime.h>
#include <cuda_bf16.h>
#include <cstdint>

#define T      4096
#define C      1024
#define NF     256
#define N3     768          // 3 * NF
#define SCALE  0.0625f      // 1/sqrt(256)
#define NEGINF -1e30f
#define JSPLIT 8
#define JCH    (T / JSPLIT) // 512

// Scratch (alloc-free rule: __device__ globals)
__device__ float g_qkv[T * N3];                        // 12 MB (only v cols used)
__device__ __nv_bfloat16 g_x_hi[T * C];                // 8 MB each
__device__ __nv_bfloat16 g_x_lo[T * C];
__device__ __nv_bfloat16 g_wT_hi[N3 * C];              // 1.5 MB each, [n][k]
__device__ __nv_bfloat16 g_wT_lo[N3 * C];
__device__ __nv_bfloat16 g_q_hi[T * NF];               // 2 MB each
__device__ __nv_bfloat16 g_q_lo[T * NF];
__device__ __nv_bfloat16 g_k_hi[T * NF];
__device__ __nv_bfloat16 g_k_lo[T * NF];
__device__ __nv_bfloat16 g_vT_hi[NF * T];              // 2 MB each, [n][k]
__device__ __nv_bfloat16 g_vT_lo[NF * T];
__device__ float g_fy[(size_t)JSPLIT * T * NF];        // 32 MB unnormalized Y partials
__device__ float g_fm[JSPLIT * T];                     // row max per chunk
__device__ float g_fl[JSPLIT * T];                     // row sum per chunk

__device__ __forceinline__ uint32_t smem_u32(const void* p) {
    uint32_t a;
    asm("{ .reg .u64 t; cvta.to.shared.u64 t, %1; cvt.u32.u64 %0, t; }" : "=r"(a) : "l"(p));
    return a;
}
__device__ __forceinline__ void ldsm_x4(uint32_t& r0, uint32_t& r1, uint32_t& r2,
                                        uint32_t& r3, uint32_t addr) {
    asm volatile("ldmatrix.sync.aligned.m8n8.x4.shared.b16 {%0,%1,%2,%3}, [%4];"
                 : "=r"(r0), "=r"(r1), "=r"(r2), "=r"(r3) : "r"(addr));
}
__device__ __forceinline__ void mma_bf16(float* c, const uint32_t* a, const uint32_t* b) {
    asm volatile(
        "mma.sync.aligned.m16n8k16.row.col.f32.bf16.bf16.f32 "
        "{%0,%1,%2,%3}, {%4,%5,%6,%7}, {%8,%9}, {%0,%1,%2,%3};"
        : "+f"(c[0]), "+f"(c[1]), "+f"(c[2]), "+f"(c[3])
        : "r"(a[0]), "r"(a[1]), "r"(a[2]), "r"(a[3]), "r"(b[0]), "r"(b[1]));
}
__device__ __forceinline__ void cp16(uint32_t smem, const void* g) {
    asm volatile("cp.async.cg.shared.global [%0], [%1], 16;" :: "r"(smem), "l"(g));
}
#define CP_COMMIT() asm volatile("cp.async.commit_group;" ::: "memory")
#define CP_WAIT(n)  asm volatile("cp.async.wait_group %0;" :: "n"(n) : "memory")

#define BKP 72                       // padded row: 64 bf16 + 8 pad (144 B)
#define APL (128 * BKP * 2)          // 18432 B: 128x64 plane
#define BPL (256 * BKP * 2)          // 36864 B: 256x64 plane
#define QKV_SMEM (2 * APL + 2 * BPL) // 110592

// ---------------------------------------------------------------------------
// Input conversions
// ---------------------------------------------------------------------------
__global__ __launch_bounds__(256) void k_cvt_x(const float* __restrict__ x) {
    const int idx = blockIdx.x * 256 + threadIdx.x;     // over T*C/4
    const int base = idx * 4;
    float4 v = *(const float4*)&x[base];
    float a[4] = {v.x, v.y, v.z, v.w};
    __nv_bfloat16 h[4], l[4];
#pragma unroll
    for (int i = 0; i < 4; i++) {
        h[i] = __float2bfloat16(a[i]);
        l[i] = __float2bfloat16(a[i] - __bfloat162float(h[i]));
    }
    *(uint2*)&g_x_hi[base] = *(uint2*)h;
    *(uint2*)&g_x_lo[base] = *(uint2*)l;
}

__global__ void k_cvt_w(const float* __restrict__ W) {
    __shared__ float tile[32][33];
    const int c0 = blockIdx.x * 32;   // n block
    const int r0 = blockIdx.y * 32;   // k block
    const int tx = threadIdx.x, ty = threadIdx.y;
#pragma unroll
    for (int yy = ty; yy < 32; yy += 8)
        tile[yy][tx] = W[(size_t)(r0 + yy) * N3 + c0 + tx];
    __syncthreads();
#pragma unroll
    for (int yy = ty; yy < 32; yy += 8) {
        const float v = tile[tx][yy];
        const __nv_bfloat16 h = __float2bfloat16(v);
        const __nv_bfloat16 l = __float2bfloat16(v - __bfloat162float(h));
        g_wT_hi[(size_t)(c0 + yy) * C + r0 + tx] = h;
        g_wT_lo[(size_t)(c0 + yy) * C + r0 + tx] = l;
    }
}

// ---------------------------------------------------------------------------
// Pass 1 (HMMA): qkv = x @ W + b.
// CTA tile 128x256, 8 warps of 64x64 (2m x 4n grid). Grid (3, 32): bn block
// 0 -> q, 1 -> k (written directly as hi/lo planes), 2 -> v (fp32).
// ---------------------------------------------------------------------------
__global__ __launch_bounds__(256, 1) void k_qkv_mma(const float* __restrict__ bias) {
    const int bm = blockIdx.y * 128;
    const int bn = blockIdx.x * 256;
    const int tid = threadIdx.x;
    extern __shared__ char dyn[];
    const uint32_t sb = smem_u32(dyn);
    const uint32_t sAh = sb, sAl = sb + APL;
    const uint32_t sBh = sb + 2 * APL, sBl = sb + 2 * APL + BPL;
    const int wid = tid >> 5, lane = tid & 31;
    const int warp_m = wid >> 2, warp_n = wid & 3;     // 2 x 4, warp tile 64x64
    const int rwA = tid >> 1, halfA = tid & 1;         // A loaders: 2 thr/row

    float acc[4][8][4];
#pragma unroll
    for (int fm = 0; fm < 4; fm++)
#pragma unroll
        for (int fn = 0; fn < 8; fn++)
#pragma unroll
            for (int e = 0; e < 4; e++) acc[fm][fn][e] = 0.f;

    for (int k0 = 0; k0 < C; k0 += 64) {
        // A: 128 rows x 64 cols (hi+lo)
#pragma unroll
        for (int j = 0; j < 4; j++) {
            const int c16 = halfA * 4 + j;
            const int gofs = k0 + c16 * 8;
            const uint32_t so = (uint32_t)(rwA * (BKP * 2) + c16 * 16);
            cp16(sAh + so, &g_x_hi[(size_t)(bm + rwA) * C + gofs]);
            cp16(sAl + so, &g_x_lo[(size_t)(bm + rwA) * C + gofs]);
        }
        // B: 256 rows x 64 cols (hi+lo), 1 thr/row
#pragma unroll
        for (int j = 0; j < 8; j++) {
            const int gofs = k0 + j * 8;
            const uint32_t so = (uint32_t)(tid * (BKP * 2) + j * 16);
            cp16(sBh + so, &g_wT_hi[(size_t)(bn + tid) * C + gofs]);
            cp16(sBl + so, &g_wT_lo[(size_t)(bn + tid) * C + gofs]);
        }
        CP_COMMIT();
        CP_WAIT(0);
        __syncthreads();

#pragma unroll
        for (int kk = 0; kk < 4; kk++) {
            uint32_t ah[4][4], al[4][4], bh[8][2], bl[8][2];
            const int a_row = warp_m * 64 + (lane & 15);
            const uint32_t a_cb = (uint32_t)(kk * 32 + (lane >> 4) * 16);
#pragma unroll
            for (int fm = 0; fm < 4; fm++) {
                const uint32_t off = (uint32_t)((a_row + fm * 16) * (BKP * 2)) + a_cb;
                ldsm_x4(ah[fm][0], ah[fm][1], ah[fm][2], ah[fm][3], sAh + off);
                ldsm_x4(al[fm][0], al[fm][1], al[fm][2], al[fm][3], sAl + off);
            }
            const int b_base = warp_n * 64 + ((lane >> 4) & 1) * 8 + (lane & 7);
            const uint32_t b_cb = (uint32_t)(kk * 32 + ((lane >> 3) & 1) * 16);
#pragma unroll
            for (int fp = 0; fp < 4; fp++) {
                const uint32_t off = (uint32_t)((b_base + fp * 16) * (BKP * 2)) + b_cb;
                ldsm_x4(bh[2 * fp][0], bh[2 * fp][1], bh[2 * fp + 1][0],
                        bh[2 * fp + 1][1], sBh + off);
                ldsm_x4(bl[2 * fp][0], bl[2 * fp][1], bl[2 * fp + 1][0],
                        bl[2 * fp + 1][1], sBl + off);
            }
#pragma unroll
            for (int fm = 0; fm < 4; fm++)
#pragma unroll
                for (int fn = 0; fn < 8; fn++) {
                    mma_bf16(acc[fm][fn], ah[fm], bh[fn]);
                    mma_bf16(acc[fm][fn], ah[fm], bl[fn]);
                    mma_bf16(acc[fm][fn], al[fm], bh[fn]);
                }
        }
        __syncthreads();
    }

    const int er = lane >> 2, ec = (lane & 3) * 2;
#pragma unroll
    for (int fm = 0; fm < 4; fm++)
#pragma unroll
        for (int fn = 0; fn < 8; fn++) {
            const int col = bn + warp_n * 64 + fn * 8 + ec;
            const float b0 = bias[col], b1 = bias[col + 1];
#pragma unroll
            for (int h = 0; h < 2; h++) {
                const int row = bm + warp_m * 64 + fm * 16 + er + h * 8;
                const float vx = acc[fm][fn][h * 2 + 0] + b0;
                const float vy = acc[fm][fn][h * 2 + 1] + b1;
                if (bn < 512) {
                    const __nv_bfloat16 hx = __float2bfloat16(vx);
                    const __nv_bfloat16 hy = __float2bfloat16(vy);
                    __nv_bfloat16 ph[2] = {hx, hy};
                    __nv_bfloat16 pl[2] = {
                        __float2bfloat16(vx - __bfloat162float(hx)),
                        __float2bfloat16(vy - __bfloat162float(hy))};
                    if (bn < 256) {
                        *(uint32_t*)&g_q_hi[row * NF + col] = *(uint32_t*)ph;
                        *(uint32_t*)&g_q_lo[row * NF + col] = *(uint32_t*)pl;
                    } else {
                        *(uint32_t*)&g_k_hi[row * NF + col - 256] = *(uint32_t*)ph;
                        *(uint32_t*)&g_k_lo[row * NF + col - 256] = *(uint32_t*)pl;
                    }
                } else {
                    float2 o; o.x = vx; o.y = vy;
                    *(float2*)&g_qkv[(size_t)row * N3 + col] = o;
                }
            }
        }
}

// v = qkv[:, 2NF:3NF]  ->  vT[n][k] hi/lo (transposed)
__global__ void k_cvt_v() {
    __shared__ float tile[32][33];
    const int c0 = blockIdx.x * 32;   // n block (0..NF)
    const int r0 = blockIdx.y * 32;   // j block (0..T)
    const int tx = threadIdx.x, ty = threadIdx.y;
#pragma unroll
    for (int yy = ty; yy < 32; yy += 8)
        tile[yy][tx] = g_qkv[(size_t)(r0 + yy) * N3 + 2 * NF + c0 + tx];
    __syncthreads();
#pragma unroll
    for (int yy = ty; yy < 32; yy += 8) {
        const float v = tile[tx][yy];
        const __nv_bfloat16 h = __float2bfloat16(v);
        const __nv_bfloat16 l = __float2bfloat16(v - __bfloat162float(h));
        g_vT_hi[(size_t)(c0 + yy) * T + r0 + tx] = h;
        g_vT_lo[(size_t)(c0 + yy) * T + r0 + tx] = l;
    }
}

// ---------------------------------------------------------------------------
// Flash attention: CTA = 64 q-rows x one j-chunk (512). 256 threads, 8 warps:
// wm = wid&3 (16-row slab), wn = wid>>2 (half of j / NF cols).
// Q loaded via early cp.async group; K group awaited before scores; V group
// awaited only at the stats merge before p@v (overlaps scores).
// ---------------------------------------------------------------------------
#define QSTR 528                     // q/k smem row bytes (264 bf16)
#define VSTR 144                     // vT / p smem row bytes (72 bf16)
#define QPL  (64 * QSTR)             // 33792
#define VPL  (256 * VSTR)            // 36864
#define PPL  (64 * VSTR)             // 9216
#define FLASH_SMEM (4 * QPL + 2 * VPL + 2 * PPL)   // 227328

__global__ __launch_bounds__(256, 1) void k_flash(const int* __restrict__ npadd_p) {
    const int n_padd = *npadd_p;
    const int bm = blockIdx.x * 64;
    const int s = blockIdx.y;

    const int al = (n_padd >> 6) << 6;
    int lo = s * JCH; if (lo < al) lo = al;
    int hi = (s + 1) * JCH; if (hi > bm + 64) hi = bm + 64;
    if (lo >= hi) return;

    extern __shared__ char dyn[];
    char* dPh = dyn + 4 * QPL + 2 * VPL;  char* dPl = dPh + PPL;
    const uint32_t sb = smem_u32(dyn);
    const uint32_t sQh = sb, sQl = sb + QPL;
    const uint32_t sKh = sb + 2 * QPL, sKl = sb + 3 * QPL;
    const uint32_t sVh = sb + 4 * QPL, sVl = sVh + VPL;
    const uint32_t sPh = sVh + 2 * VPL, sPl = sPh + PPL;

    __shared__ float sMax[2][64];
    __shared__ float sSum[2][64];

    const int tid = threadIdx.x;
    const int wid = tid >> 5, lane = tid & 31;
    const int wm = wid & 3, wn = wid >> 2;
    const int er = lane >> 2, ec = (lane & 3) * 2;
    const int r0i = wm * 16 + er;        // local row (and +8)

    // q slab (64 x 256, hi+lo) via cp.async — overlaps with first K load
#pragma unroll
    for (int t = 0; t < 8; t++) {
        const int e = t * 256 + tid;
        const int row = e >> 5, c16 = e & 31;
        cp16(sQh + row * QSTR + c16 * 16, &g_q_hi[(bm + row) * NF + c16 * 8]);
        cp16(sQl + row * QSTR + c16 * 16, &g_q_lo[(bm + row) * NF + c16 * 8]);
    }
    CP_COMMIT();

    float accY[16][4];
#pragma unroll
    for (int nf = 0; nf < 16; nf++)
#pragma unroll
        for (int e = 0; e < 4; e++) accY[nf][e] = 0.f;
    float m0 = NEGINF, m1 = NEGINF, l0 = 0.f, l1 = 0.f;

    for (int jt = lo; jt < hi; jt += 64) {
        __syncthreads();   // prior tile's MMAs done before overwriting K/V/P
        // K tile via cp.async
#pragma unroll
        for (int t = 0; t < 8; t++) {
            const int e = t * 256 + tid;
            const int row = e >> 5, c16 = e & 31;
            cp16(sKh + row * QSTR + c16 * 16, &g_k_hi[(jt + row) * NF + c16 * 8]);
            cp16(sKl + row * QSTR + c16 * 16, &g_k_lo[(jt + row) * NF + c16 * 8]);
        }
        CP_COMMIT();
        // V tile via cp.async — awaited only before p@v
#pragma unroll
        for (int t = 0; t < 8; t++) {
            const int e = t * 256 + tid;
            const int row = e >> 3, c16 = e & 7;
            cp16(sVh + row * VSTR + c16 * 16, &g_vT_hi[(size_t)row * T + jt + c16 * 8]);
            cp16(sVl + row * VSTR + c16 * 16, &g_vT_lo[(size_t)row * T + jt + c16 * 8]);
        }
        CP_COMMIT();
        CP_WAIT(1);        // q + K ready (V may still be in flight)
        __syncthreads();

        // ---- scores: S (16 x 32 per warp), K=256 ----
        float S[4][4];
#pragma unroll
        for (int fn = 0; fn < 4; fn++)
#pragma unroll
            for (int e = 0; e < 4; e++) S[fn][e] = 0.f;
#pragma unroll
        for (int kk = 0; kk < 16; kk++) {
            uint32_t ah[4], aL[4], bh[4][2], bL[4][2];
            const int a_row = wm * 16 + (lane & 15);
            const uint32_t a_off = (uint32_t)(a_row * QSTR) + kk * 32 + (lane >> 4) * 16;
            ldsm_x4(ah[0], ah[1], ah[2], ah[3], sQh + a_off);
            ldsm_x4(aL[0], aL[1], aL[2], aL[3], sQl + a_off);
            const int b_base = wn * 32 + ((lane >> 4) & 1) * 8 + (lane & 7);
            const uint32_t b_cb = (uint32_t)(kk * 32 + ((lane >> 3) & 1) * 16);
#pragma unroll
            for (int fp = 0; fp < 2; fp++) {
                const uint32_t off = (uint32_t)((b_base + fp * 16) * QSTR) + b_cb;
                ldsm_x4(bh[2 * fp][0], bh[2 * fp][1], bh[2 * fp + 1][0], bh[2 * fp + 1][1], sKh + off);
                ldsm_x4(bL[2 * fp][0], bL[2 * fp][1], bL[2 * fp + 1][0], bL[2 * fp + 1][1], sKl + off);
            }
#pragma unroll
            for (int fn = 0; fn < 4; fn++) {
                mma_bf16(S[fn], ah, bh[fn]);
                mma_bf16(S[fn], ah, bL[fn]);
                mma_bf16(S[fn], aL, bh[fn]);
            }
        }

        // ---- scale + mask + tile row-max ----
        const int gi0 = bm + r0i;   // rows gi0, gi0+8
        float tmax0 = NEGINF, tmax1 = NEGINF;
#pragma unroll
        for (int fn = 0; fn < 4; fn++) {
            const int j0 = jt + wn * 32 + fn * 8 + ec;
            S[fn][0] = (j0 <= gi0 && j0 >= n_padd) ? S[fn][0] * SCALE : NEGINF;
            S[fn][1] = (j0 + 1 <= gi0 && j0 + 1 >= n_padd) ? S[fn][1] * SCALE : NEGINF;
            S[fn][2] = (j0 <= gi0 + 8 && j0 >= n_padd) ? S[fn][2] * SCALE : NEGINF;
            S[fn][3] = (j0 + 1 <= gi0 + 8 && j0 + 1 >= n_padd) ? S[fn][3] * SCALE : NEGINF;
            tmax0 = fmaxf(tmax0, fmaxf(S[fn][0], S[fn][1]));
            tmax1 = fmaxf(tmax1, fmaxf(S[fn][2], S[fn][3]));
        }
        tmax0 = fmaxf(tmax0, __shfl_xor_sync(0xffffffffu, tmax0, 1));
        tmax0 = fmaxf(tmax0, __shfl_xor_sync(0xffffffffu, tmax0, 2));
        tmax1 = fmaxf(tmax1, __shfl_xor_sync(0xffffffffu, tmax1, 1));
        tmax1 = fmaxf(tmax1, __shfl_xor_sync(0xffffffffu, tmax1, 2));
        if ((lane & 3) == 0) { sMax[wn][r0i] = tmax0; sMax[wn][r0i + 8] = tmax1; }
        __syncthreads();
        const float rmax0 = fmaxf(sMax[0][r0i], sMax[1][r0i]);
        const float rmax1 = fmaxf(sMax[0][r0i + 8], sMax[1][r0i + 8]);

        const float mn0 = fmaxf(m0, rmax0), mn1 = fmaxf(m1, rmax1);
        const float sc0 = __expf(m0 - mn0), sc1 = __expf(m1 - mn1);

        // ---- p = exp(S - m), row sums, p -> SMEM hi/lo ----
        float ps0 = 0.f, ps1 = 0.f;
#pragma unroll
        for (int fn = 0; fn < 4; fn++) {
            const float p00 = __expf(S[fn][0] - mn0);
            const float p01 = __expf(S[fn][1] - mn0);
            const float p10 = __expf(S[fn][2] - mn1);
            const float p11 = __expf(S[fn][3] - mn1);
            ps0 += p00 + p01;
            ps1 += p10 + p11;
            const __nv_bfloat16 h00 = __float2bfloat16(p00), h01 = __float2bfloat16(p01);
            const __nv_bfloat16 h10 = __float2bfloat16(p10), h11 = __float2bfloat16(p11);
            const __nv_bfloat16 q00 = __float2bfloat16(p00 - __bfloat162float(h00));
            const __nv_bfloat16 q01 = __float2bfloat16(p01 - __bfloat162float(h01));
            const __nv_bfloat16 q10 = __float2bfloat16(p10 - __bfloat162float(h10));
            const __nv_bfloat16 q11 = __float2bfloat16(p11 - __bfloat162float(h11));
            const int pcb = (wn * 32 + fn * 8 + ec) * 2;
            __nv_bfloat16 pk[2];
            pk[0] = h00; pk[1] = h01;
            *(uint32_t*)(dPh + r0i * VSTR + pcb) = *(uint32_t*)pk;
            pk[0] = h10; pk[1] = h11;
            *(uint32_t*)(dPh + (r0i + 8) * VSTR + pcb) = *(uint32_t*)pk;
            pk[0] = q00; pk[1] = q01;
            *(uint32_t*)(dPl + r0i * VSTR + pcb) = *(uint32_t*)pk;
            pk[0] = q10; pk[1] = q11;
            *(uint32_t*)(dPl + (r0i + 8) * VSTR + pcb) = *(uint32_t*)pk;
        }
        ps0 += __shfl_xor_sync(0xffffffffu, ps0, 1);
        ps0 += __shfl_xor_sync(0xffffffffu, ps0, 2);
        ps1 += __shfl_xor_sync(0xffffffffu, ps1, 1);
        ps1 += __shfl_xor_sync(0xffffffffu, ps1, 2);
        if ((lane & 3) == 0) { sSum[wn][r0i] = ps0; sSum[wn][r0i + 8] = ps1; }
        CP_WAIT(0);        // V ready (overlapped with scores + softmax)
        __syncthreads();

        l0 = l0 * sc0 + sSum[0][r0i] + sSum[1][r0i];
        l1 = l1 * sc1 + sSum[0][r0i + 8] + sSum[1][r0i + 8];
        m0 = mn0; m1 = mn1;

        // ---- rescale Y, then Y += p @ v ----
#pragma unroll
        for (int nf = 0; nf < 16; nf++) {
            accY[nf][0] *= sc0; accY[nf][1] *= sc0;
            accY[nf][2] *= sc1; accY[nf][3] *= sc1;
        }
#pragma unroll
        for (int kk = 0; kk < 4; kk++) {
            uint32_t pah[4], paL[4];
            const int a_row = wm * 16 + (lane & 15);
            const uint32_t a_off = (uint32_t)(a_row * VSTR) + kk * 32 + (lane >> 4) * 16;
            ldsm_x4(pah[0], pah[1], pah[2], pah[3], sPh + a_off);
            ldsm_x4(paL[0], paL[1], paL[2], paL[3], sPl + a_off);
            const int b_base = wn * 128 + ((lane >> 4) & 1) * 8 + (lane & 7);
            const uint32_t b_cb = (uint32_t)(kk * 32 + ((lane >> 3) & 1) * 16);
#pragma unroll
            for (int np = 0; np < 8; np++) {
                const uint32_t off = (uint32_t)((b_base + np * 16) * VSTR) + b_cb;
                uint32_t vh[4], vL[4];
                ldsm_x4(vh[0], vh[1], vh[2], vh[3], sVh + off);
                ldsm_x4(vL[0], vL[1], vL[2], vL[3], sVl + off);
                mma_bf16(accY[2 * np], pah, &vh[0]);
                mma_bf16(accY[2 * np], pah, &vL[0]);
                mma_bf16(accY[2 * np], paL, &vh[0]);
                mma_bf16(accY[2 * np + 1], pah, &vh[2]);
                mma_bf16(accY[2 * np + 1], pah, &vL[2]);
                mma_bf16(accY[2 * np + 1], paL, &vh[2]);
            }
        }
    }

    // ---- write partials ----
    float* fy = &g_fy[(size_t)s * T * NF];
#pragma unroll
    for (int nf = 0; nf < 16; nf++) {
        const int col = wn * 128 + nf * 8 + ec;
        const int row0 = bm + r0i, row1 = row0 + 8;
        float2 o0, o1;
        o0.x = accY[nf][0]; o0.y = accY[nf][1];
        o1.x = accY[nf][2]; o1.y = accY[nf][3];
        *(float2*)&fy[(size_t)row0 * NF + col] = o0;
        *(float2*)&fy[(size_t)row1 * NF + col] = o1;
    }
    if (wn == 0 && (lane & 3) == 0) {
        g_fm[s * T + bm + r0i] = m0;
        g_fm[s * T + bm + r0i + 8] = m1;
        g_fl[s * T + bm + r0i] = l0;
        g_fl[s * T + bm + r0i + 8] = l1;
    }
}

// ---------------------------------------------------------------------------
// Combine: y_i = sum_s exp(m_s - M) Y_s / sum_s exp(m_s - M) l_s; zero pads.
// ---------------------------------------------------------------------------
__global__ __launch_bounds__(256) void k_combine(const int* __restrict__ npadd_p,
                                                 float* __restrict__ out) {
    const int n_padd = *npadd_p;
    const int idx = blockIdx.x * 256 + threadIdx.x;
    const int i = idx >> 6;
    const int c4 = (idx & 63) * 4;

    float4 o = make_float4(0.f, 0.f, 0.f, 0.f);
    if (i >= n_padd) {
        const int bm = (i >> 6) << 6;
        const int al = (n_padd >> 6) << 6;
        float M = NEGINF;
#pragma unroll
        for (int s = 0; s < JSPLIT; s++) {
            int lo = s * JCH; if (lo < al) lo = al;
            int hi = (s + 1) * JCH; if (hi > bm + 64) hi = bm + 64;
            if (lo < hi) M = fmaxf(M, g_fm[s * T + i]);
        }
        float den = 0.f;
        float4 acc = make_float4(0.f, 0.f, 0.f, 0.f);
#pragma unroll
        for (int s = 0; s < JSPLIT; s++) {
            int lo = s * JCH; if (lo < al) lo = al;
            int hi = (s + 1) * JCH; if (hi > bm + 64) hi = bm + 64;
            if (lo < hi) {
                const float w = __expf(g_fm[s * T + i] - M);
                den += w * g_fl[s * T + i];
                float4 y = *(const float4*)&g_fy[((size_t)s * T + i) * NF + c4];
                acc.x += w * y.x; acc.y += w * y.y;
                acc.z += w * y.z; acc.w += w * y.w;
            }
        }
        const float inv = 1.f / den;
        o.x = acc.x * inv; o.y = acc.y * inv;
        o.z = acc.z * inv; o.w = acc.w * inv;
    }
    *(float4*)&out[(size_t)i * NF + c4] = o;
}

// ---------------------------------------------------------------------------
extern "C" void kernel_launch(void* const* d_in, const int* in_sizes, int n_in,
                              void* d_out, int out_size) {
    const float* x = (const float*)d_in[0];
    const float* W = (const float*)d_in[1];
    const float* b = (const float*)d_in[2];
    const int* n_padd = (const int*)d_in[3];
    float* out = (float*)d_out;

    cudaFuncSetAttribute(k_qkv_mma, cudaFuncAttributeMaxDynamicSharedMemorySize, QKV_SMEM);
    cudaFuncSetAttribute(k_flash, cudaFuncAttributeMaxDynamicSharedMemorySize, FLASH_SMEM);

    k_cvt_x<<<(T * C / 4) / 256, 256>>>(x);
    k_cvt_w<<<dim3(N3 / 32, C / 32), dim3(32, 8)>>>(W);
    k_qkv_mma<<<dim3(3, T / 128), 256, QKV_SMEM>>>(b);
    k_cvt_v<<<dim3(NF / 32, T / 32), dim3(32, 8)>>>();
    k_flash<<<dim3(T / 64, JSPLIT), 256, FLASH_SMEM>>>(n_padd);
    k_combine<<<(T * NF / 4) / 256, 256>>>(n_padd, out);
}

// round 14
// speedup vs baseline: 1.0335x; 1.0335x over previous
#include <cuda_runtime.h>
#include <cuda_bf16.h>
#include <cstdint>

#define T      4096
#define C      1024
#define NF     256
#define N3     768          // 3 * NF
#define SCALE  0.0625f      // 1/sqrt(256)
#define NEGINF -1e30f
#define JSPLIT 8
#define JCH    (T / JSPLIT) // 512

// Scratch (alloc-free rule: __device__ globals)
__device__ float g_qkv[T * N3];                        // 12 MB (only v cols used)
__device__ __nv_bfloat16 g_x_hi[T * C];                // 8 MB each
__device__ __nv_bfloat16 g_x_lo[T * C];
__device__ __nv_bfloat16 g_wT_hi[N3 * C];              // 1.5 MB each, [n][k]
__device__ __nv_bfloat16 g_wT_lo[N3 * C];
__device__ __nv_bfloat16 g_q_hi[T * NF];               // 2 MB each
__device__ __nv_bfloat16 g_q_lo[T * NF];
__device__ __nv_bfloat16 g_k_hi[T * NF];
__device__ __nv_bfloat16 g_k_lo[T * NF];
__device__ __nv_bfloat16 g_vT_hi[NF * T];              // 2 MB each, [n][k]
__device__ __nv_bfloat16 g_vT_lo[NF * T];
__device__ float g_fy[(size_t)JSPLIT * T * NF];        // 32 MB unnormalized Y partials
__device__ float g_fm[JSPLIT * T];                     // row max per chunk
__device__ float g_fl[JSPLIT * T];                     // row sum per chunk

__device__ __forceinline__ uint32_t smem_u32(const void* p) {
    uint32_t a;
    asm("{ .reg .u64 t; cvta.to.shared.u64 t, %1; cvt.u32.u64 %0, t; }" : "=r"(a) : "l"(p));
    return a;
}
__device__ __forceinline__ void ldsm_x4(uint32_t& r0, uint32_t& r1, uint32_t& r2,
                                        uint32_t& r3, uint32_t addr) {
    asm volatile("ldmatrix.sync.aligned.m8n8.x4.shared.b16 {%0,%1,%2,%3}, [%4];"
                 : "=r"(r0), "=r"(r1), "=r"(r2), "=r"(r3) : "r"(addr));
}
__device__ __forceinline__ void mma_bf16(float* c, const uint32_t* a, const uint32_t* b) {
    asm volatile(
        "mma.sync.aligned.m16n8k16.row.col.f32.bf16.bf16.f32 "
        "{%0,%1,%2,%3}, {%4,%5,%6,%7}, {%8,%9}, {%0,%1,%2,%3};"
        : "+f"(c[0]), "+f"(c[1]), "+f"(c[2]), "+f"(c[3])
        : "r"(a[0]), "r"(a[1]), "r"(a[2]), "r"(a[3]), "r"(b[0]), "r"(b[1]));
}
__device__ __forceinline__ void cp16(uint32_t smem, const void* g) {
    asm volatile("cp.async.cg.shared.global [%0], [%1], 16;" :: "r"(smem), "l"(g));
}
#define CP_COMMIT() asm volatile("cp.async.commit_group;" ::: "memory")
#define CP_WAIT(n)  asm volatile("cp.async.wait_group %0;" :: "n"(n) : "memory")

#define BKP 72                       // padded row: 64 bf16 + 8 pad (144 B)
#define PLANE (128 * BKP * 2)        // 18432 B per 128x64 smem plane

// cp.async version: no register staging; single group, caller waits.
#define CP_LOAD_PLANES(Ah, Al, Bh, Bl, aRow, bRow, gstride, k0)                        \
    {                                                                                  \
        _Pragma("unroll")                                                              \
        for (int j = 0; j < 4; j++) {                                                  \
            const int c16 = half * 4 + j;                                              \
            const int gofs = (k0) + c16 * 8;                                           \
            const uint32_t so = (uint32_t)(rw * (BKP * 2) + c16 * 16);                 \
            cp16(sAh + so, &(Ah)[(size_t)(aRow) * (gstride) + gofs]);                  \
            cp16(sAl + so, &(Al)[(size_t)(aRow) * (gstride) + gofs]);                  \
            cp16(sBh + so, &(Bh)[(size_t)(bRow) * (gstride) + gofs]);                  \
            cp16(sBl + so, &(Bl)[(size_t)(bRow) * (gstride) + gofs]);                  \
        }                                                                              \
    }

#define COMPUTE_CHUNK(sAh, sAl, sBh, sBl)                                              \
    {                                                                                  \
        _Pragma("unroll")                                                              \
        for (int kk = 0; kk < 4; kk++) {                                               \
            uint32_t ah[4][4], al[4][4], bh[4][2], bl[4][2];                           \
            const int a_row = warp_m * 64 + (lane & 15);                               \
            const uint32_t a_cb = (uint32_t)(kk * 32 + (lane >> 4) * 16);              \
            _Pragma("unroll")                                                          \
            for (int fm = 0; fm < 4; fm++) {                                           \
                const uint32_t off = (uint32_t)((a_row + fm * 16) * (BKP * 2)) + a_cb; \
                ldsm_x4(ah[fm][0], ah[fm][1], ah[fm][2], ah[fm][3], (sAh) + off);      \
                ldsm_x4(al[fm][0], al[fm][1], al[fm][2], al[fm][3], (sAl) + off);      \
            }                                                                          \
            const int b_base = warp_n * 32 + ((lane >> 4) & 1) * 8 + (lane & 7);       \
            const uint32_t b_cb = (uint32_t)(kk * 32 + ((lane >> 3) & 1) * 16);        \
            _Pragma("unroll")                                                          \
            for (int fp = 0; fp < 2; fp++) {                                           \
                const uint32_t off = (uint32_t)((b_base + fp * 16) * (BKP * 2)) + b_cb;\
                ldsm_x4(bh[2 * fp][0], bh[2 * fp][1], bh[2 * fp + 1][0],               \
                        bh[2 * fp + 1][1], (sBh) + off);                               \
                ldsm_x4(bl[2 * fp][0], bl[2 * fp][1], bl[2 * fp + 1][0],               \
                        bl[2 * fp + 1][1], (sBl) + off);                               \
            }                                                                          \
            _Pragma("unroll")                                                          \
            for (int fm = 0; fm < 4; fm++)                                             \
                _Pragma("unroll")                                                      \
                for (int fn = 0; fn < 4; fn++) {                                       \
                    mma_bf16(acc[fm][fn], ah[fm], bh[fn]);                             \
                    mma_bf16(acc[fm][fn], ah[fm], bl[fn]);                             \
                    mma_bf16(acc[fm][fn], al[fm], bh[fn]);                             \
                }                                                                      \
        }                                                                              \
    }

// ---------------------------------------------------------------------------
// Input conversions
// ---------------------------------------------------------------------------
__global__ __launch_bounds__(256) void k_cvt_x(const float* __restrict__ x) {
    const int idx = blockIdx.x * 256 + threadIdx.x;     // over T*C/4
    const int base = idx * 4;
    float4 v = *(const float4*)&x[base];
    float a[4] = {v.x, v.y, v.z, v.w};
    __nv_bfloat16 h[4], l[4];
#pragma unroll
    for (int i = 0; i < 4; i++) {
        h[i] = __float2bfloat16(a[i]);
        l[i] = __float2bfloat16(a[i] - __bfloat162float(h[i]));
    }
    *(uint2*)&g_x_hi[base] = *(uint2*)h;
    *(uint2*)&g_x_lo[base] = *(uint2*)l;
}

__global__ void k_cvt_w(const float* __restrict__ W) {
    __shared__ float tile[32][33];
    const int c0 = blockIdx.x * 32;   // n block
    const int r0 = blockIdx.y * 32;   // k block
    const int tx = threadIdx.x, ty = threadIdx.y;
#pragma unroll
    for (int yy = ty; yy < 32; yy += 8)
        tile[yy][tx] = W[(size_t)(r0 + yy) * N3 + c0 + tx];
    __syncthreads();
#pragma unroll
    for (int yy = ty; yy < 32; yy += 8) {
        const float v = tile[tx][yy];
        const __nv_bfloat16 h = __float2bfloat16(v);
        const __nv_bfloat16 l = __float2bfloat16(v - __bfloat162float(h));
        g_wT_hi[(size_t)(c0 + yy) * C + r0 + tx] = h;
        g_wT_lo[(size_t)(c0 + yy) * C + r0 + tx] = l;
    }
}

// ---------------------------------------------------------------------------
// Pass 1 (HMMA): qkv = x @ W + b.  q/k written directly as hi/lo planes.
// 128x128 CTA tile, 8 warps of 64x32 (R12 configuration — best measured).
// ---------------------------------------------------------------------------
__global__ __launch_bounds__(256) void k_qkv_mma(const float* __restrict__ bias) {
    const int bm = blockIdx.y * 128;
    const int bn = blockIdx.x * 128;
    const int tid = threadIdx.x;
    extern __shared__ char dyn[];
    const uint32_t sb = smem_u32(dyn);
    const uint32_t sAh = sb, sAl = sb + PLANE, sBh = sb + 2 * PLANE, sBl = sb + 3 * PLANE;
    const int wid = tid >> 5, lane = tid & 31;
    const int warp_m = wid >> 2, warp_n = wid & 3;
    const int rw = tid >> 1, half = tid & 1;

    float acc[4][4][4];
#pragma unroll
    for (int fm = 0; fm < 4; fm++)
#pragma unroll
        for (int fn = 0; fn < 4; fn++)
#pragma unroll
            for (int e = 0; e < 4; e++) acc[fm][fn][e] = 0.f;

    for (int k0 = 0; k0 < C; k0 += 64) {
        CP_LOAD_PLANES(g_x_hi, g_x_lo, g_wT_hi, g_wT_lo, bm + rw, bn + rw, C, k0);
        CP_COMMIT();
        CP_WAIT(0);
        __syncthreads();
        COMPUTE_CHUNK(sAh, sAl, sBh, sBl);
        __syncthreads();
    }

    const int er = lane >> 2, ec = (lane & 3) * 2;
#pragma unroll
    for (int fm = 0; fm < 4; fm++)
#pragma unroll
        for (int fn = 0; fn < 4; fn++) {
            const int col = bn + warp_n * 32 + fn * 8 + ec;
            const float b0 = bias[col], b1 = bias[col + 1];
#pragma unroll
            for (int h = 0; h < 2; h++) {
                const int row = bm + warp_m * 64 + fm * 16 + er + h * 8;
                const float vx = acc[fm][fn][h * 2 + 0] + b0;
                const float vy = acc[fm][fn][h * 2 + 1] + b1;
                if (bn < 512) {
                    const __nv_bfloat16 hx = __float2bfloat16(vx);
                    const __nv_bfloat16 hy = __float2bfloat16(vy);
                    __nv_bfloat16 ph[2] = {hx, hy};
                    __nv_bfloat16 pl[2] = {
                        __float2bfloat16(vx - __bfloat162float(hx)),
                        __float2bfloat16(vy - __bfloat162float(hy))};
                    if (bn < 256) {
                        *(uint32_t*)&g_q_hi[row * NF + col] = *(uint32_t*)ph;
                        *(uint32_t*)&g_q_lo[row * NF + col] = *(uint32_t*)pl;
                    } else {
                        *(uint32_t*)&g_k_hi[row * NF + col - 256] = *(uint32_t*)ph;
                        *(uint32_t*)&g_k_lo[row * NF + col - 256] = *(uint32_t*)pl;
                    }
                } else {
                    float2 o; o.x = vx; o.y = vy;
                    *(float2*)&g_qkv[(size_t)row * N3 + col] = o;
                }
            }
        }
}

// v = qkv[:, 2NF:3NF]  ->  vT[n][k] hi/lo (transposed)
__global__ void k_cvt_v() {
    __shared__ float tile[32][33];
    const int c0 = blockIdx.x * 32;   // n block (0..NF)
    const int r0 = blockIdx.y * 32;   // j block (0..T)
    const int tx = threadIdx.x, ty = threadIdx.y;
#pragma unroll
    for (int yy = ty; yy < 32; yy += 8)
        tile[yy][tx] = g_qkv[(size_t)(r0 + yy) * N3 + 2 * NF + c0 + tx];
    __syncthreads();
#pragma unroll
    for (int yy = ty; yy < 32; yy += 8) {
        const float v = tile[tx][yy];
        const __nv_bfloat16 h = __float2bfloat16(v);
        const __nv_bfloat16 l = __float2bfloat16(v - __bfloat162float(h));
        g_vT_hi[(size_t)(c0 + yy) * T + r0 + tx] = h;
        g_vT_lo[(size_t)(c0 + yy) * T + r0 + tx] = l;
    }
}

// ---------------------------------------------------------------------------
// Flash attention: CTA = 64 q-rows x one j-chunk (512). 256 threads, 8 warps.
// q_hi A-fragments hoisted into registers once (invariant across j-tiles).
// K awaited before scores; V awaited only before p@v (overlaps scores).
// ---------------------------------------------------------------------------
#define QSTR 528                     // q/k smem row bytes (264 bf16)
#define VSTR 144                     // vT / p smem row bytes (72 bf16)
#define QPL  (64 * QSTR)             // 33792
#define VPL  (256 * VSTR)            // 36864
#define PPL  (64 * VSTR)             // 9216
#define FLASH_SMEM (4 * QPL + 2 * VPL + 2 * PPL)   // 227328

__global__ __launch_bounds__(256, 1) void k_flash(const int* __restrict__ npadd_p) {
    const int n_padd = *npadd_p;
    const int bm = blockIdx.x * 64;
    const int s = blockIdx.y;

    const int al = (n_padd >> 6) << 6;
    int lo = s * JCH; if (lo < al) lo = al;
    int hi = (s + 1) * JCH; if (hi > bm + 64) hi = bm + 64;
    if (lo >= hi) return;

    extern __shared__ char dyn[];
    char* dQh = dyn;            char* dQl = dyn + QPL;
    char* dPh = dyn + 4 * QPL + 2 * VPL;  char* dPl = dPh + PPL;
    const uint32_t sb = smem_u32(dyn);
    const uint32_t sQh = sb, sQl = sb + QPL;
    const uint32_t sKh = sb + 2 * QPL, sKl = sb + 3 * QPL;
    const uint32_t sVh = sb + 4 * QPL, sVl = sVh + VPL;
    const uint32_t sPh = sVh + 2 * VPL, sPl = sPh + PPL;

    __shared__ float sMax[2][64];
    __shared__ float sSum[2][64];

    const int tid = threadIdx.x;
    const int wid = tid >> 5, lane = tid & 31;
    const int wm = wid & 3, wn = wid >> 2;
    const int er = lane >> 2, ec = (lane & 3) * 2;
    const int r0i = wm * 16 + er;        // local row (and +8)

    // load q slab once (64 x 256, hi+lo)
#pragma unroll
    for (int t = 0; t < 8; t++) {
        const int e = t * 256 + tid;
        const int row = e >> 5, c16 = e & 31;
        *(uint4*)(dQh + row * QSTR + c16 * 16) = *(const uint4*)&g_q_hi[(bm + row) * NF + c16 * 8];
        *(uint4*)(dQl + row * QSTR + c16 * 16) = *(const uint4*)&g_q_lo[(bm + row) * NF + c16 * 8];
    }

    float accY[16][4];
#pragma unroll
    for (int nf = 0; nf < 16; nf++)
#pragma unroll
        for (int e = 0; e < 4; e++) accY[nf][e] = 0.f;
    float m0 = NEGINF, m1 = NEGINF, l0 = 0.f, l1 = 0.f;

    uint32_t qh[16][4];           // hoisted q_hi A-fragments (loaded once)
    bool qh_loaded = false;

    for (int jt = lo; jt < hi; jt += 64) {
        __syncthreads();   // prior tile's MMAs done before overwriting K/V/P
        // K tile via cp.async
#pragma unroll
        for (int t = 0; t < 8; t++) {
            const int e = t * 256 + tid;
            const int row = e >> 5, c16 = e & 31;
            cp16(sKh + row * QSTR + c16 * 16, &g_k_hi[(jt + row) * NF + c16 * 8]);
            cp16(sKl + row * QSTR + c16 * 16, &g_k_lo[(jt + row) * NF + c16 * 8]);
        }
        CP_COMMIT();
        // V tile via cp.async — awaited only before p@v
#pragma unroll
        for (int t = 0; t < 8; t++) {
            const int e = t * 256 + tid;
            const int row = e >> 3, c16 = e & 7;
            cp16(sVh + row * VSTR + c16 * 16, &g_vT_hi[(size_t)row * T + jt + c16 * 8]);
            cp16(sVl + row * VSTR + c16 * 16, &g_vT_lo[(size_t)row * T + jt + c16 * 8]);
        }
        CP_COMMIT();
        CP_WAIT(1);        // K ready (V may still be in flight)
        __syncthreads();

        if (!qh_loaded) {
            qh_loaded = true;
            const int a_row = wm * 16 + (lane & 15);
#pragma unroll
            for (int kk = 0; kk < 16; kk++) {
                const uint32_t a_off = (uint32_t)(a_row * QSTR) + kk * 32 + (lane >> 4) * 16;
                ldsm_x4(qh[kk][0], qh[kk][1], qh[kk][2], qh[kk][3], sQh + a_off);
            }
        }

        // ---- scores: S (16 x 32 per warp), K=256 ----
        float S[4][4];
#pragma unroll
        for (int fn = 0; fn < 4; fn++)
#pragma unroll
            for (int e = 0; e < 4; e++) S[fn][e] = 0.f;
#pragma unroll
        for (int kk = 0; kk < 16; kk++) {
            uint32_t aL[4], bh[4][2], bL[4][2];
            const int a_row = wm * 16 + (lane & 15);
            const uint32_t a_off = (uint32_t)(a_row * QSTR) + kk * 32 + (lane >> 4) * 16;
            ldsm_x4(aL[0], aL[1], aL[2], aL[3], sQl + a_off);
            const int b_base = wn * 32 + ((lane >> 4) & 1) * 8 + (lane & 7);
            const uint32_t b_cb = (uint32_t)(kk * 32 + ((lane >> 3) & 1) * 16);
#pragma unroll
            for (int fp = 0; fp < 2; fp++) {
                const uint32_t off = (uint32_t)((b_base + fp * 16) * QSTR) + b_cb;
                ldsm_x4(bh[2 * fp][0], bh[2 * fp][1], bh[2 * fp + 1][0], bh[2 * fp + 1][1], sKh + off);
                ldsm_x4(bL[2 * fp][0], bL[2 * fp][1], bL[2 * fp + 1][0], bL[2 * fp + 1][1], sKl + off);
            }
#pragma unroll
            for (int fn = 0; fn < 4; fn++) {
                mma_bf16(S[fn], qh[kk], bh[fn]);
                mma_bf16(S[fn], qh[kk], bL[fn]);
                mma_bf16(S[fn], aL, bh[fn]);
            }
        }

        // ---- scale + mask + tile row-max ----
        const int gi0 = bm + r0i;   // rows gi0, gi0+8
        float tmax0 = NEGINF, tmax1 = NEGINF;
#pragma unroll
        for (int fn = 0; fn < 4; fn++) {
            const int j0 = jt + wn * 32 + fn * 8 + ec;
            S[fn][0] = (j0 <= gi0 && j0 >= n_padd) ? S[fn][0] * SCALE : NEGINF;
            S[fn][1] = (j0 + 1 <= gi0 && j0 + 1 >= n_padd) ? S[fn][1] * SCALE : NEGINF;
            S[fn][2] = (j0 <= gi0 + 8 && j0 >= n_padd) ? S[fn][2] * SCALE : NEGINF;
            S[fn][3] = (j0 + 1 <= gi0 + 8 && j0 + 1 >= n_padd) ? S[fn][3] * SCALE : NEGINF;
            tmax0 = fmaxf(tmax0, fmaxf(S[fn][0], S[fn][1]));
            tmax1 = fmaxf(tmax1, fmaxf(S[fn][2], S[fn][3]));
        }
        tmax0 = fmaxf(tmax0, __shfl_xor_sync(0xffffffffu, tmax0, 1));
        tmax0 = fmaxf(tmax0, __shfl_xor_sync(0xffffffffu, tmax0, 2));
        tmax1 = fmaxf(tmax1, __shfl_xor_sync(0xffffffffu, tmax1, 1));
        tmax1 = fmaxf(tmax1, __shfl_xor_sync(0xffffffffu, tmax1, 2));
        if ((lane & 3) == 0) { sMax[wn][r0i] = tmax0; sMax[wn][r0i + 8] = tmax1; }
        __syncthreads();
        const float rmax0 = fmaxf(sMax[0][r0i], sMax[1][r0i]);
        const float rmax1 = fmaxf(sMax[0][r0i + 8], sMax[1][r0i + 8]);

        const float mn0 = fmaxf(m0, rmax0), mn1 = fmaxf(m1, rmax1);
        const float sc0 = __expf(m0 - mn0), sc1 = __expf(m1 - mn1);

        // ---- p = exp(S - m), row sums, p -> SMEM hi/lo ----
        float ps0 = 0.f, ps1 = 0.f;
#pragma unroll
        for (int fn = 0; fn < 4; fn++) {
            const float p00 = __expf(S[fn][0] - mn0);
            const float p01 = __expf(S[fn][1] - mn0);
            const float p10 = __expf(S[fn][2] - mn1);
            const float p11 = __expf(S[fn][3] - mn1);
            ps0 += p00 + p01;
            ps1 += p10 + p11;
            const __nv_bfloat16 h00 = __float2bfloat16(p00), h01 = __float2bfloat16(p01);
            const __nv_bfloat16 h10 = __float2bfloat16(p10), h11 = __float2bfloat16(p11);
            const __nv_bfloat16 q00 = __float2bfloat16(p00 - __bfloat162float(h00));
            const __nv_bfloat16 q01 = __float2bfloat16(p01 - __bfloat162float(h01));
            const __nv_bfloat16 q10 = __float2bfloat16(p10 - __bfloat162float(h10));
            const __nv_bfloat16 q11 = __float2bfloat16(p11 - __bfloat162float(h11));
            const int pcb = (wn * 32 + fn * 8 + ec) * 2;
            __nv_bfloat16 pk[2];
            pk[0] = h00; pk[1] = h01;
            *(uint32_t*)(dPh + r0i * VSTR + pcb) = *(uint32_t*)pk;
            pk[0] = h10; pk[1] = h11;
            *(uint32_t*)(dPh + (r0i + 8) * VSTR + pcb) = *(uint32_t*)pk;
            pk[0] = q00; pk[1] = q01;
            *(uint32_t*)(dPl + r0i * VSTR + pcb) = *(uint32_t*)pk;
            pk[0] = q10; pk[1] = q11;
            *(uint32_t*)(dPl + (r0i + 8) * VSTR + pcb) = *(uint32_t*)pk;
        }
        ps0 += __shfl_xor_sync(0xffffffffu, ps0, 1);
        ps0 += __shfl_xor_sync(0xffffffffu, ps0, 2);
        ps1 += __shfl_xor_sync(0xffffffffu, ps1, 1);
        ps1 += __shfl_xor_sync(0xffffffffu, ps1, 2);
        if ((lane & 3) == 0) { sSum[wn][r0i] = ps0; sSum[wn][r0i + 8] = ps1; }
        CP_WAIT(0);        // V ready (overlapped with scores + softmax)
        __syncthreads();

        l0 = l0 * sc0 + sSum[0][r0i] + sSum[1][r0i];
        l1 = l1 * sc1 + sSum[0][r0i + 8] + sSum[1][r0i + 8];
        m0 = mn0; m1 = mn1;

        // ---- rescale Y, then Y += p @ v ----
#pragma unroll
        for (int nf = 0; nf < 16; nf++) {
            accY[nf][0] *= sc0; accY[nf][1] *= sc0;
            accY[nf][2] *= sc1; accY[nf][3] *= sc1;
        }
#pragma unroll
        for (int kk = 0; kk < 4; kk++) {
            uint32_t pah[4], paL[4];
            const int a_row = wm * 16 + (lane & 15);
            const uint32_t a_off = (uint32_t)(a_row * VSTR) + kk * 32 + (lane >> 4) * 16;
            ldsm_x4(pah[0], pah[1], pah[2], pah[3], sPh + a_off);
            ldsm_x4(paL[0], paL[1], paL[2], paL[3], sPl + a_off);
            const int b_base = wn * 128 + ((lane >> 4) & 1) * 8 + (lane & 7);
            const uint32_t b_cb = (uint32_t)(kk * 32 + ((lane >> 3) & 1) * 16);
#pragma unroll
            for (int np = 0; np < 8; np++) {
                const uint32_t off = (uint32_t)((b_base + np * 16) * VSTR) + b_cb;
                uint32_t vh[4], vL[4];
                ldsm_x4(vh[0], vh[1], vh[2], vh[3], sVh + off);
                ldsm_x4(vL[0], vL[1], vL[2], vL[3], sVl + off);
                mma_bf16(accY[2 * np], pah, &vh[0]);
                mma_bf16(accY[2 * np], pah, &vL[0]);
                mma_bf16(accY[2 * np], paL, &vh[0]);
                mma_bf16(accY[2 * np + 1], pah, &vh[2]);
                mma_bf16(accY[2 * np + 1], pah, &vL[2]);
                mma_bf16(accY[2 * np + 1], paL, &vh[2]);
            }
        }
    }

    // ---- write partials ----
    float* fy = &g_fy[(size_t)s * T * NF];
#pragma unroll
    for (int nf = 0; nf < 16; nf++) {
        const int col = wn * 128 + nf * 8 + ec;
        const int row0 = bm + r0i, row1 = row0 + 8;
        float2 o0, o1;
        o0.x = accY[nf][0]; o0.y = accY[nf][1];
        o1.x = accY[nf][2]; o1.y = accY[nf][3];
        *(float2*)&fy[(size_t)row0 * NF + col] = o0;
        *(float2*)&fy[(size_t)row1 * NF + col] = o1;
    }
    if (wn == 0 && (lane & 3) == 0) {
        g_fm[s * T + bm + r0i] = m0;
        g_fm[s * T + bm + r0i + 8] = m1;
        g_fl[s * T + bm + r0i] = l0;
        g_fl[s * T + bm + r0i + 8] = l1;
    }
}

// ---------------------------------------------------------------------------
// Combine: y_i = sum_s exp(m_s - M) Y_s / sum_s exp(m_s - M) l_s; zero pads.
// ---------------------------------------------------------------------------
__global__ __launch_bounds__(256) void k_combine(const int* __restrict__ npadd_p,
                                                 float* __restrict__ out) {
    const int n_padd = *npadd_p;
    const int idx = blockIdx.x * 256 + threadIdx.x;
    const int i = idx >> 6;
    const int c4 = (idx & 63) * 4;

    float4 o = make_float4(0.f, 0.f, 0.f, 0.f);
    if (i >= n_padd) {
        const int bm = (i >> 6) << 6;
        const int al = (n_padd >> 6) << 6;
        float M = NEGINF;
#pragma unroll
        for (int s = 0; s < JSPLIT; s++) {
            int lo = s * JCH; if (lo < al) lo = al;
            int hi = (s + 1) * JCH; if (hi > bm + 64) hi = bm + 64;
            if (lo < hi) M = fmaxf(M, g_fm[s * T + i]);
        }
        float den = 0.f;
        float4 acc = make_float4(0.f, 0.f, 0.f, 0.f);
#pragma unroll
        for (int s = 0; s < JSPLIT; s++) {
            int lo = s * JCH; if (lo < al) lo = al;
            int hi = (s + 1) * JCH; if (hi > bm + 64) hi = bm + 64;
            if (lo < hi) {
                const float w = __expf(g_fm[s * T + i] - M);
                den += w * g_fl[s * T + i];
                float4 y = *(const float4*)&g_fy[((size_t)s * T + i) * NF + c4];
                acc.x += w * y.x; acc.y += w * y.y;
                acc.z += w * y.z; acc.w += w * y.w;
            }
        }
        const float inv = 1.f / den;
        o.x = acc.x * inv; o.y = acc.y * inv;
        o.z = acc.z * inv; o.w = acc.w * inv;
    }
    *(float4*)&out[(size_t)i * NF + c4] = o;
}

// ---------------------------------------------------------------------------
extern "C" void kernel_launch(void* const* d_in, const int* in_sizes, int n_in,
                              void* d_out, int out_size) {
    const float* x = (const float*)d_in[0];
    const float* W = (const float*)d_in[1];
    const float* b = (const float*)d_in[2];
    const int* n_padd = (const int*)d_in[3];
    float* out = (float*)d_out;

    cudaFuncSetAttribute(k_qkv_mma, cudaFuncAttributeMaxDynamicSharedMemorySize, 4 * PLANE);
    cudaFuncSetAttribute(k_flash, cudaFuncAttributeMaxDynamicSharedMemorySize, FLASH_SMEM);

    k_cvt_x<<<(T * C / 4) / 256, 256>>>(x);
    k_cvt_w<<<dim3(N3 / 32, C / 32), dim3(32, 8)>>>(W);
    k_qkv_mma<<<dim3(N3 / 128, T / 128), 256, 4 * PLANE>>>(b);
    k_cvt_v<<<dim3(NF / 32, T / 32), dim3(32, 8)>>>();
    k_flash<<<dim3(T / 64, JSPLIT), 256, FLASH_SMEM>>>(n_padd);
    k_combine<<<(T * NF / 4) / 256, 256>>>(n_padd, out);
}

// round 15
// speedup vs baseline: 1.0344x; 1.0008x over previous
#include <cuda_runtime.h>
#include <cuda_bf16.h>
#include <cstdint>

#define T      4096
#define C      1024
#define NF     256
#define N3     768          // 3 * NF
#define SCALE  0.0625f      // 1/sqrt(256)
#define NEGINF -1e30f
#define JSPLIT 8
#define JCH    (T / JSPLIT) // 512

// Scratch (alloc-free rule: __device__ globals)
__device__ float g_qkv[T * N3];                        // 12 MB (only v cols used)
__device__ __nv_bfloat16 g_x_hi[T * C];                // 8 MB each
__device__ __nv_bfloat16 g_x_lo[T * C];
__device__ __nv_bfloat16 g_wT_hi[N3 * C];              // 1.5 MB each, [n][k]
__device__ __nv_bfloat16 g_wT_lo[N3 * C];
__device__ __nv_bfloat16 g_q_hi[T * NF];               // 2 MB each
__device__ __nv_bfloat16 g_q_lo[T * NF];
__device__ __nv_bfloat16 g_k_hi[T * NF];
__device__ __nv_bfloat16 g_k_lo[T * NF];
__device__ __nv_bfloat16 g_vT_hi[NF * T];              // 2 MB each, [n][k]
__device__ __nv_bfloat16 g_vT_lo[NF * T];
__device__ float g_fy[(size_t)JSPLIT * T * NF];        // 32 MB unnormalized Y partials
__device__ float g_fm[JSPLIT * T];                     // row max per chunk
__device__ float g_fl[JSPLIT * T];                     // row sum per chunk

__device__ __forceinline__ uint32_t smem_u32(const void* p) {
    uint32_t a;
    asm("{ .reg .u64 t; cvta.to.shared.u64 t, %1; cvt.u32.u64 %0, t; }" : "=r"(a) : "l"(p));
    return a;
}
__device__ __forceinline__ void ldsm_x4(uint32_t& r0, uint32_t& r1, uint32_t& r2,
                                        uint32_t& r3, uint32_t addr) {
    asm volatile("ldmatrix.sync.aligned.m8n8.x4.shared.b16 {%0,%1,%2,%3}, [%4];"
                 : "=r"(r0), "=r"(r1), "=r"(r2), "=r"(r3) : "r"(addr));
}
__device__ __forceinline__ void mma_bf16(float* c, const uint32_t* a, const uint32_t* b) {
    asm volatile(
        "mma.sync.aligned.m16n8k16.row.col.f32.bf16.bf16.f32 "
        "{%0,%1,%2,%3}, {%4,%5,%6,%7}, {%8,%9}, {%0,%1,%2,%3};"
        : "+f"(c[0]), "+f"(c[1]), "+f"(c[2]), "+f"(c[3])
        : "r"(a[0]), "r"(a[1]), "r"(a[2]), "r"(a[3]), "r"(b[0]), "r"(b[1]));
}
__device__ __forceinline__ void cp16(uint32_t smem, const void* g) {
    asm volatile("cp.async.cg.shared.global [%0], [%1], 16;" :: "r"(smem), "l"(g));
}
#define CP_COMMIT() asm volatile("cp.async.commit_group;" ::: "memory")
#define CP_WAIT(n)  asm volatile("cp.async.wait_group %0;" :: "n"(n) : "memory")

#define BKP 72                       // padded row: 64 bf16 + 8 pad (144 B)
#define PLANE (128 * BKP * 2)        // 18432 B per 128x64 smem plane

// cp.async version: no register staging; single group, caller waits.
#define CP_LOAD_PLANES(Ah, Al, Bh, Bl, aRow, bRow, gstride, k0)                        \
    {                                                                                  \
        _Pragma("unroll")                                                              \
        for (int j = 0; j < 4; j++) {                                                  \
            const int c16 = half * 4 + j;                                              \
            const int gofs = (k0) + c16 * 8;                                           \
            const uint32_t so = (uint32_t)(rw * (BKP * 2) + c16 * 16);                 \
            cp16(sAh + so, &(Ah)[(size_t)(aRow) * (gstride) + gofs]);                  \
            cp16(sAl + so, &(Al)[(size_t)(aRow) * (gstride) + gofs]);                  \
            cp16(sBh + so, &(Bh)[(size_t)(bRow) * (gstride) + gofs]);                  \
            cp16(sBl + so, &(Bl)[(size_t)(bRow) * (gstride) + gofs]);                  \
        }                                                                              \
    }

#define COMPUTE_CHUNK(sAh, sAl, sBh, sBl)                                              \
    {                                                                                  \
        _Pragma("unroll")                                                              \
        for (int kk = 0; kk < 4; kk++) {                                               \
            uint32_t ah[4][4], al[4][4], bh[4][2], bl[4][2];                           \
            const int a_row = warp_m * 64 + (lane & 15);                               \
            const uint32_t a_cb = (uint32_t)(kk * 32 + (lane >> 4) * 16);              \
            _Pragma("unroll")                                                          \
            for (int fm = 0; fm < 4; fm++) {                                           \
                const uint32_t off = (uint32_t)((a_row + fm * 16) * (BKP * 2)) + a_cb; \
                ldsm_x4(ah[fm][0], ah[fm][1], ah[fm][2], ah[fm][3], (sAh) + off);      \
                ldsm_x4(al[fm][0], al[fm][1], al[fm][2], al[fm][3], (sAl) + off);      \
            }                                                                          \
            const int b_base = warp_n * 32 + ((lane >> 4) & 1) * 8 + (lane & 7);       \
            const uint32_t b_cb = (uint32_t)(kk * 32 + ((lane >> 3) & 1) * 16);        \
            _Pragma("unroll")                                                          \
            for (int fp = 0; fp < 2; fp++) {                                           \
                const uint32_t off = (uint32_t)((b_base + fp * 16) * (BKP * 2)) + b_cb;\
                ldsm_x4(bh[2 * fp][0], bh[2 * fp][1], bh[2 * fp + 1][0],               \
                        bh[2 * fp + 1][1], (sBh) + off);                               \
                ldsm_x4(bl[2 * fp][0], bl[2 * fp][1], bl[2 * fp + 1][0],               \
                        bl[2 * fp + 1][1], (sBl) + off);                               \
            }                                                                          \
            _Pragma("unroll")                                                          \
            for (int fm = 0; fm < 4; fm++)                                             \
                _Pragma("unroll")                                                      \
                for (int fn = 0; fn < 4; fn++) {                                       \
                    mma_bf16(acc[fm][fn], ah[fm], bh[fn]);                             \
                    mma_bf16(acc[fm][fn], ah[fm], bl[fn]);                             \
                    mma_bf16(acc[fm][fn], al[fm], bh[fn]);                             \
                }                                                                      \
        }                                                                              \
    }

// ---------------------------------------------------------------------------
// Input conversions
// ---------------------------------------------------------------------------
__global__ __launch_bounds__(256) void k_cvt_x(const float* __restrict__ x) {
    const int idx = blockIdx.x * 256 + threadIdx.x;     // over T*C/4
    const int base = idx * 4;
    float4 v = *(const float4*)&x[base];
    float a[4] = {v.x, v.y, v.z, v.w};
    __nv_bfloat16 h[4], l[4];
#pragma unroll
    for (int i = 0; i < 4; i++) {
        h[i] = __float2bfloat16(a[i]);
        l[i] = __float2bfloat16(a[i] - __bfloat162float(h[i]));
    }
    *(uint2*)&g_x_hi[base] = *(uint2*)h;
    *(uint2*)&g_x_lo[base] = *(uint2*)l;
}

__global__ void k_cvt_w(const float* __restrict__ W) {
    __shared__ float tile[32][33];
    const int c0 = blockIdx.x * 32;   // n block
    const int r0 = blockIdx.y * 32;   // k block
    const int tx = threadIdx.x, ty = threadIdx.y;
#pragma unroll
    for (int yy = ty; yy < 32; yy += 8)
        tile[yy][tx] = W[(size_t)(r0 + yy) * N3 + c0 + tx];
    __syncthreads();
#pragma unroll
    for (int yy = ty; yy < 32; yy += 8) {
        const float v = tile[tx][yy];
        const __nv_bfloat16 h = __float2bfloat16(v);
        const __nv_bfloat16 l = __float2bfloat16(v - __bfloat162float(h));
        g_wT_hi[(size_t)(c0 + yy) * C + r0 + tx] = h;
        g_wT_lo[(size_t)(c0 + yy) * C + r0 + tx] = l;
    }
}

// ---------------------------------------------------------------------------
// Pass 1 (HMMA): qkv = x @ W + b.  q/k written directly as hi/lo planes.
// 128x128 CTA tile, 8 warps of 64x32 (best measured config).
// ---------------------------------------------------------------------------
__global__ __launch_bounds__(256) void k_qkv_mma(const float* __restrict__ bias) {
    const int bm = blockIdx.y * 128;
    const int bn = blockIdx.x * 128;
    const int tid = threadIdx.x;
    extern __shared__ char dyn[];
    const uint32_t sb = smem_u32(dyn);
    const uint32_t sAh = sb, sAl = sb + PLANE, sBh = sb + 2 * PLANE, sBl = sb + 3 * PLANE;
    const int wid = tid >> 5, lane = tid & 31;
    const int warp_m = wid >> 2, warp_n = wid & 3;
    const int rw = tid >> 1, half = tid & 1;

    float acc[4][4][4];
#pragma unroll
    for (int fm = 0; fm < 4; fm++)
#pragma unroll
        for (int fn = 0; fn < 4; fn++)
#pragma unroll
            for (int e = 0; e < 4; e++) acc[fm][fn][e] = 0.f;

    for (int k0 = 0; k0 < C; k0 += 64) {
        CP_LOAD_PLANES(g_x_hi, g_x_lo, g_wT_hi, g_wT_lo, bm + rw, bn + rw, C, k0);
        CP_COMMIT();
        CP_WAIT(0);
        __syncthreads();
        COMPUTE_CHUNK(sAh, sAl, sBh, sBl);
        __syncthreads();
    }

    const int er = lane >> 2, ec = (lane & 3) * 2;
#pragma unroll
    for (int fm = 0; fm < 4; fm++)
#pragma unroll
        for (int fn = 0; fn < 4; fn++) {
            const int col = bn + warp_n * 32 + fn * 8 + ec;
            const float b0 = bias[col], b1 = bias[col + 1];
#pragma unroll
            for (int h = 0; h < 2; h++) {
                const int row = bm + warp_m * 64 + fm * 16 + er + h * 8;
                const float vx = acc[fm][fn][h * 2 + 0] + b0;
                const float vy = acc[fm][fn][h * 2 + 1] + b1;
                if (bn < 512) {
                    const __nv_bfloat16 hx = __float2bfloat16(vx);
                    const __nv_bfloat16 hy = __float2bfloat16(vy);
                    __nv_bfloat16 ph[2] = {hx, hy};
                    __nv_bfloat16 pl[2] = {
                        __float2bfloat16(vx - __bfloat162float(hx)),
                        __float2bfloat16(vy - __bfloat162float(hy))};
                    if (bn < 256) {
                        *(uint32_t*)&g_q_hi[row * NF + col] = *(uint32_t*)ph;
                        *(uint32_t*)&g_q_lo[row * NF + col] = *(uint32_t*)pl;
                    } else {
                        *(uint32_t*)&g_k_hi[row * NF + col - 256] = *(uint32_t*)ph;
                        *(uint32_t*)&g_k_lo[row * NF + col - 256] = *(uint32_t*)pl;
                    }
                } else {
                    float2 o; o.x = vx; o.y = vy;
                    *(float2*)&g_qkv[(size_t)row * N3 + col] = o;
                }
            }
        }
}

// v = qkv[:, 2NF:3NF]  ->  vT[n][k] hi/lo (transposed)
__global__ void k_cvt_v() {
    __shared__ float tile[32][33];
    const int c0 = blockIdx.x * 32;   // n block (0..NF)
    const int r0 = blockIdx.y * 32;   // j block (0..T)
    const int tx = threadIdx.x, ty = threadIdx.y;
#pragma unroll
    for (int yy = ty; yy < 32; yy += 8)
        tile[yy][tx] = g_qkv[(size_t)(r0 + yy) * N3 + 2 * NF + c0 + tx];
    __syncthreads();
#pragma unroll
    for (int yy = ty; yy < 32; yy += 8) {
        const float v = tile[tx][yy];
        const __nv_bfloat16 h = __float2bfloat16(v);
        const __nv_bfloat16 l = __float2bfloat16(v - __bfloat162float(h));
        g_vT_hi[(size_t)(c0 + yy) * T + r0 + tx] = h;
        g_vT_lo[(size_t)(c0 + yy) * T + r0 + tx] = l;
    }
}

// ---------------------------------------------------------------------------
// Flash attention: CTA = 64 q-rows x one j-chunk (512). 256 threads, 8 warps.
// BOTH q planes hoisted to registers; the two freed Q SMEM planes become a
// second K buffer -> K(j+1) prefetch overlaps softmax + P + p@v of tile j.
// V single-buffered: issued at tile top, awaited before p@v (overlaps scores).
// ---------------------------------------------------------------------------
#define QSTR 528                     // k smem row bytes (264 bf16)
#define VSTR 144                     // vT / p smem row bytes (72 bf16)
#define QPL  (64 * QSTR)             // 33792
#define VPL  (256 * VSTR)            // 36864
#define PPL  (64 * VSTR)             // 9216
#define FLASH_SMEM (4 * QPL + 2 * VPL + 2 * PPL)   // 227328

__global__ __launch_bounds__(256, 1) void k_flash(const int* __restrict__ npadd_p) {
    const int n_padd = *npadd_p;
    const int bm = blockIdx.x * 64;
    const int s = blockIdx.y;

    const int al = (n_padd >> 6) << 6;
    int lo = s * JCH; if (lo < al) lo = al;
    int hi = (s + 1) * JCH; if (hi > bm + 64) hi = bm + 64;
    if (lo >= hi) return;

    extern __shared__ char dyn[];
    char* dPh = dyn + 4 * QPL + 2 * VPL;  char* dPl = dPh + PPL;
    const uint32_t sb = smem_u32(dyn);
    // K double buffer: buf p at planes {2p, 2p+1}
    const uint32_t sVh = sb + 4 * QPL, sVl = sVh + VPL;
    const uint32_t sPh = sVh + 2 * VPL, sPl = sPh + PPL;

    __shared__ float sMax[2][64];
    __shared__ float sSum[2][64];

    const int tid = threadIdx.x;
    const int wid = tid >> 5, lane = tid & 31;
    const int wm = wid & 3, wn = wid >> 2;
    const int er = lane >> 2, ec = (lane & 3) * 2;
    const int r0i = wm * 16 + er;        // local row (and +8)

    // ---- stage q into K buffers, hoist to registers, then free buffers ----
#pragma unroll
    for (int t = 0; t < 8; t++) {
        const int e = t * 256 + tid;
        const int row = e >> 5, c16 = e & 31;
        *(uint4*)(dyn + 0 * QPL + row * QSTR + c16 * 16) = *(const uint4*)&g_q_hi[(bm + row) * NF + c16 * 8];
        *(uint4*)(dyn + 1 * QPL + row * QSTR + c16 * 16) = *(const uint4*)&g_q_lo[(bm + row) * NF + c16 * 8];
    }
    __syncthreads();
    uint32_t qh[16][4], ql[16][4];
    {
        const int a_row = wm * 16 + (lane & 15);
#pragma unroll
        for (int kk = 0; kk < 16; kk++) {
            const uint32_t a_off = (uint32_t)(a_row * QSTR) + kk * 32 + (lane >> 4) * 16;
            ldsm_x4(qh[kk][0], qh[kk][1], qh[kk][2], qh[kk][3], sb + 0 * QPL + a_off);
            ldsm_x4(ql[kk][0], ql[kk][1], ql[kk][2], ql[kk][3], sb + 1 * QPL + a_off);
        }
    }
    __syncthreads();

    // ---- prefetch first K into buffer 0 ----
#pragma unroll
    for (int t = 0; t < 8; t++) {
        const int e = t * 256 + tid;
        const int row = e >> 5, c16 = e & 31;
        cp16(sb + 0 * QPL + row * QSTR + c16 * 16, &g_k_hi[(lo + row) * NF + c16 * 8]);
        cp16(sb + 1 * QPL + row * QSTR + c16 * 16, &g_k_lo[(lo + row) * NF + c16 * 8]);
    }
    CP_COMMIT();
    int p = 0;

    float accY[16][4];
#pragma unroll
    for (int nf = 0; nf < 16; nf++)
#pragma unroll
        for (int e = 0; e < 4; e++) accY[nf][e] = 0.f;
    float m0 = NEGINF, m1 = NEGINF, l0 = 0.f, l1 = 0.f;

    for (int jt = lo; jt < hi; jt += 64) {
        const bool last = (jt + 64 >= hi);
        __syncthreads();   // prior p@v done -> V buffer safe to overwrite
        // V(jt) via cp.async — awaited before p@v
#pragma unroll
        for (int t = 0; t < 8; t++) {
            const int e = t * 256 + tid;
            const int row = e >> 3, c16 = e & 7;
            cp16(sVh + row * VSTR + c16 * 16, &g_vT_hi[(size_t)row * T + jt + c16 * 8]);
            cp16(sVl + row * VSTR + c16 * 16, &g_vT_lo[(size_t)row * T + jt + c16 * 8]);
        }
        CP_COMMIT();
        CP_WAIT(1);        // K(jt) ready (V in flight)
        __syncthreads();

        const uint32_t sKh = sb + (2 * p) * QPL, sKl = sb + (2 * p + 1) * QPL;

        // ---- scores: S (16 x 32 per warp), K=256, q from registers ----
        float S[4][4];
#pragma unroll
        for (int fn = 0; fn < 4; fn++)
#pragma unroll
            for (int e = 0; e < 4; e++) S[fn][e] = 0.f;
#pragma unroll
        for (int kk = 0; kk < 16; kk++) {
            uint32_t bh[4][2], bL[4][2];
            const int b_base = wn * 32 + ((lane >> 4) & 1) * 8 + (lane & 7);
            const uint32_t b_cb = (uint32_t)(kk * 32 + ((lane >> 3) & 1) * 16);
#pragma unroll
            for (int fp = 0; fp < 2; fp++) {
                const uint32_t off = (uint32_t)((b_base + fp * 16) * QSTR) + b_cb;
                ldsm_x4(bh[2 * fp][0], bh[2 * fp][1], bh[2 * fp + 1][0], bh[2 * fp + 1][1], sKh + off);
                ldsm_x4(bL[2 * fp][0], bL[2 * fp][1], bL[2 * fp + 1][0], bL[2 * fp + 1][1], sKl + off);
            }
#pragma unroll
            for (int fn = 0; fn < 4; fn++) {
                mma_bf16(S[fn], qh[kk], bh[fn]);
                mma_bf16(S[fn], qh[kk], bL[fn]);
                mma_bf16(S[fn], ql[kk], bh[fn]);
            }
        }

        // ---- prefetch K(jt+64) into other buffer (overlaps rest of tile) ----
        if (!last) {
            const uint32_t nKh = sb + (2 * (p ^ 1)) * QPL, nKl = sb + (2 * (p ^ 1) + 1) * QPL;
#pragma unroll
            for (int t = 0; t < 8; t++) {
                const int e = t * 256 + tid;
                const int row = e >> 5, c16 = e & 31;
                cp16(nKh + row * QSTR + c16 * 16, &g_k_hi[(jt + 64 + row) * NF + c16 * 8]);
                cp16(nKl + row * QSTR + c16 * 16, &g_k_lo[(jt + 64 + row) * NF + c16 * 8]);
            }
            CP_COMMIT();
        }

        // ---- scale + mask + tile row-max ----
        const int gi0 = bm + r0i;   // rows gi0, gi0+8
        float tmax0 = NEGINF, tmax1 = NEGINF;
#pragma unroll
        for (int fn = 0; fn < 4; fn++) {
            const int j0 = jt + wn * 32 + fn * 8 + ec;
            S[fn][0] = (j0 <= gi0 && j0 >= n_padd) ? S[fn][0] * SCALE : NEGINF;
            S[fn][1] = (j0 + 1 <= gi0 && j0 + 1 >= n_padd) ? S[fn][1] * SCALE : NEGINF;
            S[fn][2] = (j0 <= gi0 + 8 && j0 >= n_padd) ? S[fn][2] * SCALE : NEGINF;
            S[fn][3] = (j0 + 1 <= gi0 + 8 && j0 + 1 >= n_padd) ? S[fn][3] * SCALE : NEGINF;
            tmax0 = fmaxf(tmax0, fmaxf(S[fn][0], S[fn][1]));
            tmax1 = fmaxf(tmax1, fmaxf(S[fn][2], S[fn][3]));
        }
        tmax0 = fmaxf(tmax0, __shfl_xor_sync(0xffffffffu, tmax0, 1));
        tmax0 = fmaxf(tmax0, __shfl_xor_sync(0xffffffffu, tmax0, 2));
        tmax1 = fmaxf(tmax1, __shfl_xor_sync(0xffffffffu, tmax1, 1));
        tmax1 = fmaxf(tmax1, __shfl_xor_sync(0xffffffffu, tmax1, 2));
        if ((lane & 3) == 0) { sMax[wn][r0i] = tmax0; sMax[wn][r0i + 8] = tmax1; }
        __syncthreads();
        const float rmax0 = fmaxf(sMax[0][r0i], sMax[1][r0i]);
        const float rmax1 = fmaxf(sMax[0][r0i + 8], sMax[1][r0i + 8]);

        const float mn0 = fmaxf(m0, rmax0), mn1 = fmaxf(m1, rmax1);
        const float sc0 = __expf(m0 - mn0), sc1 = __expf(m1 - mn1);

        // ---- p = exp(S - m), row sums, p -> SMEM hi/lo ----
        float ps0 = 0.f, ps1 = 0.f;
#pragma unroll
        for (int fn = 0; fn < 4; fn++) {
            const float p00 = __expf(S[fn][0] - mn0);
            const float p01 = __expf(S[fn][1] - mn0);
            const float p10 = __expf(S[fn][2] - mn1);
            const float p11 = __expf(S[fn][3] - mn1);
            ps0 += p00 + p01;
            ps1 += p10 + p11;
            const __nv_bfloat16 h00 = __float2bfloat16(p00), h01 = __float2bfloat16(p01);
            const __nv_bfloat16 h10 = __float2bfloat16(p10), h11 = __float2bfloat16(p11);
            const __nv_bfloat16 q00 = __float2bfloat16(p00 - __bfloat162float(h00));
            const __nv_bfloat16 q01 = __float2bfloat16(p01 - __bfloat162float(h01));
            const __nv_bfloat16 q10 = __float2bfloat16(p10 - __bfloat162float(h10));
            const __nv_bfloat16 q11 = __float2bfloat16(p11 - __bfloat162float(h11));
            const int pcb = (wn * 32 + fn * 8 + ec) * 2;
            __nv_bfloat16 pk[2];
            pk[0] = h00; pk[1] = h01;
            *(uint32_t*)(dPh + r0i * VSTR + pcb) = *(uint32_t*)pk;
            pk[0] = h10; pk[1] = h11;
            *(uint32_t*)(dPh + (r0i + 8) * VSTR + pcb) = *(uint32_t*)pk;
            pk[0] = q00; pk[1] = q01;
            *(uint32_t*)(dPl + r0i * VSTR + pcb) = *(uint32_t*)pk;
            pk[0] = q10; pk[1] = q11;
            *(uint32_t*)(dPl + (r0i + 8) * VSTR + pcb) = *(uint32_t*)pk;
        }
        ps0 += __shfl_xor_sync(0xffffffffu, ps0, 1);
        ps0 += __shfl_xor_sync(0xffffffffu, ps0, 2);
        ps1 += __shfl_xor_sync(0xffffffffu, ps1, 1);
        ps1 += __shfl_xor_sync(0xffffffffu, ps1, 2);
        if ((lane & 3) == 0) { sSum[wn][r0i] = ps0; sSum[wn][r0i + 8] = ps1; }
        if (last) { CP_WAIT(0); } else { CP_WAIT(1); }   // V ready; K(j+1) may fly
        __syncthreads();

        l0 = l0 * sc0 + sSum[0][r0i] + sSum[1][r0i];
        l1 = l1 * sc1 + sSum[0][r0i + 8] + sSum[1][r0i + 8];
        m0 = mn0; m1 = mn1;

        // ---- rescale Y, then Y += p @ v ----
#pragma unroll
        for (int nf = 0; nf < 16; nf++) {
            accY[nf][0] *= sc0; accY[nf][1] *= sc0;
            accY[nf][2] *= sc1; accY[nf][3] *= sc1;
        }
#pragma unroll
        for (int kk = 0; kk < 4; kk++) {
            uint32_t pah[4], paL[4];
            const int a_row = wm * 16 + (lane & 15);
            const uint32_t a_off = (uint32_t)(a_row * VSTR) + kk * 32 + (lane >> 4) * 16;
            ldsm_x4(pah[0], pah[1], pah[2], pah[3], sPh + a_off);
            ldsm_x4(paL[0], paL[1], paL[2], paL[3], sPl + a_off);
            const int b_base = wn * 128 + ((lane >> 4) & 1) * 8 + (lane & 7);
            const uint32_t b_cb = (uint32_t)(kk * 32 + ((lane >> 3) & 1) * 16);
#pragma unroll
            for (int np = 0; np < 8; np++) {
                const uint32_t off = (uint32_t)((b_base + np * 16) * VSTR) + b_cb;
                uint32_t vh[4], vL[4];
                ldsm_x4(vh[0], vh[1], vh[2], vh[3], sVh + off);
                ldsm_x4(vL[0], vL[1], vL[2], vL[3], sVl + off);
                mma_bf16(accY[2 * np], pah, &vh[0]);
                mma_bf16(accY[2 * np], pah, &vL[0]);
                mma_bf16(accY[2 * np], paL, &vh[0]);
                mma_bf16(accY[2 * np + 1], pah, &vh[2]);
                mma_bf16(accY[2 * np + 1], pah, &vL[2]);
                mma_bf16(accY[2 * np + 1], paL, &vh[2]);
            }
        }
        p ^= 1;
    }

    // ---- write partials ----
    float* fy = &g_fy[(size_t)s * T * NF];
#pragma unroll
    for (int nf = 0; nf < 16; nf++) {
        const int col = wn * 128 + nf * 8 + ec;
        const int row0 = bm + r0i, row1 = row0 + 8;
        float2 o0, o1;
        o0.x = accY[nf][0]; o0.y = accY[nf][1];
        o1.x = accY[nf][2]; o1.y = accY[nf][3];
        *(float2*)&fy[(size_t)row0 * NF + col] = o0;
        *(float2*)&fy[(size_t)row1 * NF + col] = o1;
    }
    if (wn == 0 && (lane & 3) == 0) {
        g_fm[s * T + bm + r0i] = m0;
        g_fm[s * T + bm + r0i + 8] = m1;
        g_fl[s * T + bm + r0i] = l0;
        g_fl[s * T + bm + r0i + 8] = l1;
    }
}

// ---------------------------------------------------------------------------
// Combine: y_i = sum_s exp(m_s - M) Y_s / sum_s exp(m_s - M) l_s; zero pads.
// ---------------------------------------------------------------------------
__global__ __launch_bounds__(256) void k_combine(const int* __restrict__ npadd_p,
                                                 float* __restrict__ out) {
    const int n_padd = *npadd_p;
    const int idx = blockIdx.x * 256 + threadIdx.x;
    const int i = idx >> 6;
    const int c4 = (idx & 63) * 4;

    float4 o = make_float4(0.f, 0.f, 0.f, 0.f);
    if (i >= n_padd) {
        const int bm = (i >> 6) << 6;
        const int al = (n_padd >> 6) << 6;
        float M = NEGINF;
#pragma unroll
        for (int s = 0; s < JSPLIT; s++) {
            int lo = s * JCH; if (lo < al) lo = al;
            int hi = (s + 1) * JCH; if (hi > bm + 64) hi = bm + 64;
            if (lo < hi) M = fmaxf(M, g_fm[s * T + i]);
        }
        float den = 0.f;
        float4 acc = make_float4(0.f, 0.f, 0.f, 0.f);
#pragma unroll
        for (int s = 0; s < JSPLIT; s++) {
            int lo = s * JCH; if (lo < al) lo = al;
            int hi = (s + 1) * JCH; if (hi > bm + 64) hi = bm + 64;
            if (lo < hi) {
                const float w = __expf(g_fm[s * T + i] - M);
                den += w * g_fl[s * T + i];
                float4 y = *(const float4*)&g_fy[((size_t)s * T + i) * NF + c4];
                acc.x += w * y.x; acc.y += w * y.y;
                acc.z += w * y.z; acc.w += w * y.w;
            }
        }
        const float inv = 1.f / den;
        o.x = acc.x * inv; o.y = acc.y * inv;
        o.z = acc.z * inv; o.w = acc.w * inv;
    }
    *(float4*)&out[(size_t)i * NF + c4] = o;
}

// ---------------------------------------------------------------------------
extern "C" void kernel_launch(void* const* d_in, const int* in_sizes, int n_in,
                              void* d_out, int out_size) {
    const float* x = (const float*)d_in[0];
    const float* W = (const float*)d_in[1];
    const float* b = (const float*)d_in[2];
    const int* n_padd = (const int*)d_in[3];
    float* out = (float*)d_out;

    cudaFuncSetAttribute(k_qkv_mma, cudaFuncAttributeMaxDynamicSharedMemorySize, 4 * PLANE);
    cudaFuncSetAttribute(k_flash, cudaFuncAttributeMaxDynamicSharedMemorySize, FLASH_SMEM);

    k_cvt_x<<<(T * C / 4) / 256, 256>>>(x);
    k_cvt_w<<<dim3(N3 / 32, C / 32), dim3(32, 8)>>>(W);
    k_qkv_mma<<<dim3(N3 / 128, T / 128), 256, 4 * PLANE>>>(b);
    k_cvt_v<<<dim3(NF / 32, T / 32), dim3(32, 8)>>>();
    k_flash<<<dim3(T / 64, JSPLIT), 256, FLASH_SMEM>>>(n_padd);
    k_combine<<<(T * NF / 4) / 256, 256>>>(n_padd, out);
}